// round 15
// baseline (speedup 1.0000x reference)
#include <cuda_runtime.h>
#include <cuda_bf16.h>

// Fused single-kernel deterministic reduction: out = sum(x) * a * b
// x: 8192*8192 fp32 (d_in[0]), a,b: scalar fp32 (d_in[1], d_in[2]).
//
// Mainloop is the EXACT R2 stage1 configuration — the fastest reduction
// loop ever measured in this session (~41us by subtraction): grid-stride
// over float4 with long long induction, #pragma unroll 4, plain cached
// loads, 1184 x 256, NO launch_bounds min-blocks hint (that hint crushed
// regs to 20 in R6 and serialized the loads). Fused deterministic
// last-block tail replaces the 4.7us second launch.

#define R_BLOCKS  1184
#define R_THREADS 256

__device__ float g_partials[R_BLOCKS];
__device__ unsigned int g_count = 0;   // self-resetting: graph-replay safe

__device__ __forceinline__ float block_reduce(float s)
{
    #pragma unroll
    for (int o = 16; o > 0; o >>= 1)
        s += __shfl_xor_sync(0xffffffffu, s, o);

    __shared__ float sh[R_THREADS / 32];
    int lane = threadIdx.x & 31;
    int warp = threadIdx.x >> 5;
    if (lane == 0) sh[warp] = s;
    __syncthreads();

    if (warp == 0) {
        s = (lane < (R_THREADS / 32)) ? sh[lane] : 0.f;
        #pragma unroll
        for (int o = 16; o > 0; o >>= 1)
            s += __shfl_xor_sync(0xffffffffu, s, o);
    }
    return s;  // valid in warp 0 lane 0
}

__global__ __launch_bounds__(R_THREADS) void reduce_fused(
    const float4* __restrict__ x4, long long n4,
    const float* __restrict__ a, const float* __restrict__ b,
    float* __restrict__ out)
{
    float s0 = 0.f, s1 = 0.f, s2 = 0.f, s3 = 0.f;
    long long idx    = (long long)blockIdx.x * blockDim.x + threadIdx.x;
    long long stride = (long long)gridDim.x * blockDim.x;

    // R2's exact loop: 4 independent float4 loads per unrolled body,
    // 4 accumulator lanes keep FADD chains short.
    #pragma unroll 4
    for (long long i = idx; i < n4; i += stride) {
        float4 v = x4[i];
        s0 += v.x; s1 += v.y; s2 += v.z; s3 += v.w;
    }
    float s = block_reduce((s0 + s1) + (s2 + s3));

    __shared__ bool is_last;
    if (threadIdx.x == 0) {
        g_partials[blockIdx.x] = s;
        __threadfence();
        unsigned int prev = atomicAdd(&g_count, 1u);
        is_last = (prev == (unsigned)gridDim.x - 1u);
    }
    __syncthreads();

    if (is_last) {
        // Deterministic final fold: fixed per-thread strided order.
        float t = 0.f;
        for (int i = threadIdx.x; i < R_BLOCKS; i += R_THREADS)
            t += g_partials[i];
        t = block_reduce(t);
        if (threadIdx.x == 0) {
            out[0] = t * a[0] * b[0];
            g_count = 0;   // reset for next graph replay
        }
    }
}

extern "C" void kernel_launch(void* const* d_in, const int* in_sizes, int n_in,
                              void* d_out, int out_size)
{
    const float4* x4 = (const float4*)d_in[0];
    const float* a   = (const float*)d_in[1];
    const float* b   = (const float*)d_in[2];
    float* out       = (float*)d_out;

    long long n4 = (long long)in_sizes[0] >> 2;  // 8192*8192/4 = 2^24

    reduce_fused<<<R_BLOCKS, R_THREADS>>>(x4, n4, a, b, out);
}